// round 1
// baseline (speedup 1.0000x reference)
#include <cuda_runtime.h>

#define NB   4      // nodes per block
#define NT   128    // threads per block (1 warp per node)
#define SS   16     // neighbors per node
#define IND  128    // input dim
#define OUTD 64     // output dim
#define ED   32     // edge dim

// Precomputed W2 @ a_n  (128 floats)
__device__ float g_w2a[IND];

__global__ void w2a_kernel(const float* __restrict__ W2, const float* __restrict__ a) {
    int k = threadIdx.x;                       // 0..127
    float s = 0.f;
#pragma unroll
    for (int d = 0; d < OUTD; ++d)
        s = fmaf(W2[k * OUTD + d], a[OUTD + d], s);
    g_w2a[k] = s;
}

__global__ __launch_bounds__(NT)
void gat_fused(const float* __restrict__ input,
               const float* __restrict__ neigh,
               const float* __restrict__ eef,
               const float* __restrict__ W,
               const float* __restrict__ W2,
               const float* __restrict__ a,
               float* __restrict__ out, int N) {
    __shared__ float4 s_neigh[NB * SS * (IND / 4)];   // 2048 f4 = 32 KB
    __shared__ float4 s_ee[NB * SS * (ED / 4)];       //  512 f4 =  8 KB
    __shared__ float  s_in[NB][IND];                  //  2 KB
    __shared__ float  s_agg[NB][IND];                 //  2 KB   (total 44 KB)

    const int tid   = threadIdx.x;
    const int node0 = blockIdx.x * NB;
    const int nv    = min(NB, N - node0);

    // ---- cooperative tile loads (coalesced float4 streams) ----
    {
        const float4* g = (const float4*)neigh + (size_t)node0 * (SS * IND / 4);
        const int tot = nv * (SS * IND / 4);
#pragma unroll
        for (int i = 0; i < (NB * SS * IND / 4) / NT; ++i) {   // 16 iters
            int idx = tid + i * NT;
            if (idx < tot) s_neigh[idx] = g[idx];
        }
    }
    {
        const float4* g = (const float4*)eef + (size_t)node0 * (SS * ED / 4);
        const int tot = nv * (SS * ED / 4);
#pragma unroll
        for (int i = 0; i < (NB * SS * ED / 4) / NT; ++i) {    // 4 iters
            int idx = tid + i * NT;
            if (idx < tot) s_ee[idx] = g[idx];
        }
    }
    {
        const float4* g = (const float4*)input + (size_t)node0 * (IND / 4);
        const int tot = nv * (IND / 4);                        // 128 == NT
        if (tid < tot) ((float4*)s_in)[tid] = g[tid];
    }
    __syncthreads();   // the only block-wide barrier

    const int w = tid >> 5, lane = tid & 31;
    const int n = node0 + w;
    if (n >= N) return;   // whole-warp exit; no further block barriers

    // ---- x = input[n] @ W  (this warp: cols lane, lane+32) ----
    float x0 = 0.f, x1 = 0.f;
    {
        const float* Wp = W + lane;
#pragma unroll 8
        for (int k = 0; k < IND; ++k) {
            float iv = s_in[w][k];                 // LDS broadcast
            x0 = fmaf(iv, Wp[k * OUTD],      x0);  // coalesced LDG, L1-resident
            x1 = fmaf(iv, Wp[k * OUTD + 32], x1);
        }
    }
    // sx = x . a_x  (warp butterfly reduce)
    float p = fmaf(x0, a[lane], x1 * a[lane + 32]);
#pragma unroll
    for (int o = 16; o; o >>= 1) p += __shfl_xor_sync(0xffffffffu, p, o);
    const float sx = p;

    // ---- scores[s] = sx + neigh_row . w2a + ee_row . a_e ----
    const float4  w2a4 = ((const float4*)g_w2a)[lane];   // lane's 4 ks
    const float   ae   = a[2 * OUTD + lane];
    const float4* nbp  = s_neigh + w * (SS * IND / 4);
    const float*  ebp  = (const float*)(s_ee + w * (SS * ED / 4));

    float sc[SS];
#pragma unroll
    for (int s = 0; s < SS; ++s) {
        float4 v = nbp[s * (IND / 4) + lane];
        float part = v.x * w2a4.x;
        part = fmaf(v.y, w2a4.y, part);
        part = fmaf(v.z, w2a4.z, part);
        part = fmaf(v.w, w2a4.w, part);
        part = fmaf(ebp[s * ED + lane], ae, part);
#pragma unroll
        for (int o = 16; o; o >>= 1) part += __shfl_xor_sync(0xffffffffu, part, o);
        sc[s] = part + sx;   // identical value in all lanes
    }

    // ---- leaky relu + softmax over S=16 ----
    float mx = -3.0e38f;
#pragma unroll
    for (int s = 0; s < SS; ++s) {
        float v = sc[s];
        v = v > 0.f ? v : 0.8f * v;
        sc[s] = v;
        mx = fmaxf(mx, v);
    }
    float den = 0.f;
#pragma unroll
    for (int s = 0; s < SS; ++s) {
        float e = expf(sc[s] - mx);
        sc[s] = e;
        den += e;
    }
    const float inv = 1.f / den;

    // ---- attention-weighted aggregation in 128-dim (pre-projection) ----
    float4 agg = make_float4(0.f, 0.f, 0.f, 0.f);
    float  he  = 0.f;
#pragma unroll
    for (int s = 0; s < SS; ++s) {
        float att = sc[s] * inv;
        float4 v = nbp[s * (IND / 4) + lane];
        agg.x = fmaf(att, v.x, agg.x);
        agg.y = fmaf(att, v.y, agg.y);
        agg.z = fmaf(att, v.z, agg.z);
        agg.w = fmaf(att, v.w, agg.w);
        he = fmaf(att, ebp[s * ED + lane], he);
    }
    ((float4*)s_agg[w])[lane] = agg;
    __syncwarp();

    // ---- h_prime = agg @ W2 ----
    float h0 = 0.f, h1 = 0.f;
    {
        const float* Wp = W2 + lane;
#pragma unroll 8
        for (int k = 0; k < IND; ++k) {
            float av = s_agg[w][k];                // LDS broadcast
            h0 = fmaf(av, Wp[k * OUTD],      h0);
            h1 = fmaf(av, Wp[k * OUTD + 32], h1);
        }
    }

    // ---- output: [x(64) | h_prime(64) | h_edge(32)] ----
    float* o = out + (size_t)n * (2 * OUTD + ED);
    o[lane]       = x0;
    o[lane + 32]  = x1;
    o[64 + lane]  = h0;
    o[96 + lane]  = h1;
    o[128 + lane] = he;
}

extern "C" void kernel_launch(void* const* d_in, const int* in_sizes, int n_in,
                              void* d_out, int out_size) {
    const float* input = (const float*)d_in[0];
    const float* neigh = (const float*)d_in[1];
    const float* ee    = (const float*)d_in[2];
    const float* W     = (const float*)d_in[3];
    const float* W2    = (const float*)d_in[4];
    const float* a     = (const float*)d_in[5];
    float* out = (float*)d_out;

    const int N = in_sizes[0] / IND;          // 50000
    w2a_kernel<<<1, IND>>>(W2, a);
    const int blocks = (N + NB - 1) / NB;     // 12500
    gat_fused<<<blocks, NT>>>(input, neigh, ee, W, W2, a, out, N);
}

// round 2
// speedup vs baseline: 1.0685x; 1.0685x over previous
#include <cuda_runtime.h>

#define SS   16
#define IND  128
#define OUTD 64
#define ED   32
#define OSTR 160    // output row stride: [x(64) | h_prime(64) | h_edge(32)]

// ---- device-global scratch (allocation-free) ----
__device__ float g_w2a[IND];                 // W2 @ a_n
__device__ float g_Wt [OUTD * IND];          // W^T  (col-major: [d][k])
__device__ float g_W2t[OUTD * IND];          // W2^T
__device__ float g_agg[50176 * IND];         // attention-aggregated 128-dim vectors

// ---------------------------------------------------------------------------
// Prelude: w2a = W2 @ a_n ; transpose W, W2 for vectorized weight loads.
// ---------------------------------------------------------------------------
__global__ void prelude(const float* __restrict__ W, const float* __restrict__ W2,
                        const float* __restrict__ a) {
    int t = threadIdx.x;                       // 128 threads
    float s = 0.f;
#pragma unroll
    for (int d = 0; d < OUTD; ++d)
        s = fmaf(W2[t * OUTD + d], a[OUTD + d], s);
    g_w2a[t] = s;

    for (int i = t; i < IND * OUTD; i += 128) {
        int k = i / OUTD, d = i % OUTD;
        g_Wt [d * IND + k] = W [i];
        g_W2t[d * IND + k] = W2[i];
    }
}

// ---------------------------------------------------------------------------
// Tiled GEMM: Y[m, yoff + c] = X[m, :] @ Wt[c, :]   (K = 128, Ncols = 64)
// 16 rows/block, 128 threads: thread t -> col c = t&63, row-group g = t>>6 (8 rows).
// Weight: 1 float4 LDG per 4 k (L1/L2 resident). Inputs: uniform LDS broadcasts.
// mode 0: X = input,  Wt = g_Wt,  yoff = 0
// mode 1: X = g_agg,  Wt = g_W2t, yoff = 64
// ---------------------------------------------------------------------------
__global__ __launch_bounds__(128)
void gemm16(const float* __restrict__ Xp, float* __restrict__ Y, int mode, int M) {
    __shared__ float4 s_x[16 * (IND / 4)];     // 8 KB

    const float* X  = mode ? g_agg  : Xp;
    const float* Wt = mode ? g_W2t  : g_Wt;
    const int    yoff = mode ? OUTD : 0;

    const int t  = threadIdx.x;
    const int m0 = blockIdx.x * 16;
    const int nv = min(16, M - m0);

    const float4* xg  = (const float4*)X + (size_t)m0 * (IND / 4);
    const int     tot = nv * (IND / 4);
#pragma unroll
    for (int i = 0; i < 4; ++i) {
        int idx = t + i * 128;
        if (idx < tot) s_x[idx] = xg[idx];
    }
    __syncthreads();

    const int c = t & 63, g = t >> 6;
    float acc[8] = {0.f, 0.f, 0.f, 0.f, 0.f, 0.f, 0.f, 0.f};
    const float4* wr = (const float4*)(Wt + c * IND);
    const float4* xb = s_x + g * 8 * (IND / 4);

#pragma unroll 4
    for (int k4 = 0; k4 < IND / 4; ++k4) {
        float4 wv = wr[k4];                    // LDG.128, cache-resident
#pragma unroll
        for (int m = 0; m < 8; ++m) {
            float4 xv = xb[m * (IND / 4) + k4]; // LDS.128 uniform broadcast
            acc[m] = fmaf(wv.x, xv.x, acc[m]);
            acc[m] = fmaf(wv.y, xv.y, acc[m]);
            acc[m] = fmaf(wv.z, xv.z, acc[m]);
            acc[m] = fmaf(wv.w, xv.w, acc[m]);
        }
    }

    const int mlim = nv - g * 8;
#pragma unroll
    for (int m = 0; m < 8; ++m)
        if (m < mlim)
            Y[(size_t)(m0 + g * 8 + m) * OSTR + yoff + c] = acc[m];
}

// ---------------------------------------------------------------------------
// Attention: warp-per-node online softmax, single streaming pass over neigh.
// Reads x (cols 0..63 of out, written by gemm16 mode 0) for the sx term.
// Writes g_agg[n][0..127] (normalized 128-dim aggregate) and h_edge to out.
// ---------------------------------------------------------------------------
__global__ __launch_bounds__(256)
void attn(const float* __restrict__ neigh, const float* __restrict__ ee,
          const float* __restrict__ a, float* out, int N) {
    const int w    = threadIdx.x >> 5;
    const int lane = threadIdx.x & 31;
    const int n    = blockIdx.x * 8 + w;
    if (n >= N) return;                        // whole-warp exit; no block barriers

    // sx = (x . a_x), x read back from out row n
    const float* xr = out + (size_t)n * OSTR;
    float p = fmaf(xr[lane], a[lane], xr[lane + 32] * a[lane + 32]);
#pragma unroll
    for (int o = 16; o; o >>= 1) p += __shfl_xor_sync(0xffffffffu, p, o);
    const float sx = p;

    const float4 w2a4 = ((const float4*)g_w2a)[lane];
    const float  ae   = a[2 * OUTD + lane];
    const float4* nb  = (const float4*)neigh + (size_t)n * (SS * IND / 4);
    const float*  eb  = ee + (size_t)n * (SS * ED);

    float  m = -3.0e38f, den = 0.f, he = 0.f;
    float4 agg = make_float4(0.f, 0.f, 0.f, 0.f);

    float4 v  = nb[lane];                      // prefetch s = 0
    float  ev = eb[lane];

#pragma unroll
    for (int s = 0; s < SS; ++s) {
        float4 vn; float evn;
        if (s + 1 < SS) {                      // prefetch s+1 (overlaps reduce chain)
            vn  = nb[(s + 1) * (IND / 4) + lane];
            evn = eb[(s + 1) * ED + lane];
        }
        // score partial: neigh . w2a + ee . a_e
        float part = v.x * w2a4.x;
        part = fmaf(v.y, w2a4.y, part);
        part = fmaf(v.z, w2a4.z, part);
        part = fmaf(v.w, w2a4.w, part);
        part = fmaf(ev, ae, part);
#pragma unroll
        for (int o = 16; o; o >>= 1) part += __shfl_xor_sync(0xffffffffu, part, o);

        float sc = part + sx;
        sc = sc > 0.f ? sc : 0.8f * sc;        // leaky relu

        // online softmax update
        float mn   = fmaxf(m, sc);
        float corr = __expf(m - mn);
        float pe   = __expf(sc - mn);
        den   = fmaf(den,   corr, pe);
        agg.x = fmaf(agg.x, corr, pe * v.x);
        agg.y = fmaf(agg.y, corr, pe * v.y);
        agg.z = fmaf(agg.z, corr, pe * v.z);
        agg.w = fmaf(agg.w, corr, pe * v.w);
        he    = fmaf(he,    corr, pe * ev);
        m = mn;

        if (s + 1 < SS) { v = vn; ev = evn; }
    }

    const float inv = 1.f / den;
    float4 o4 = make_float4(agg.x * inv, agg.y * inv, agg.z * inv, agg.w * inv);
    ((float4*)g_agg)[(size_t)n * (IND / 4) + lane] = o4;
    out[(size_t)n * OSTR + 2 * OUTD + lane] = he * inv;
}

// ---------------------------------------------------------------------------
extern "C" void kernel_launch(void* const* d_in, const int* in_sizes, int n_in,
                              void* d_out, int out_size) {
    const float* input = (const float*)d_in[0];
    const float* neigh = (const float*)d_in[1];
    const float* ee    = (const float*)d_in[2];
    const float* W     = (const float*)d_in[3];
    const float* W2    = (const float*)d_in[4];
    const float* a     = (const float*)d_in[5];
    float* out = (float*)d_out;

    const int N = in_sizes[0] / IND;           // 50000

    prelude<<<1, 128>>>(W, W2, a);
    gemm16<<<(N + 15) / 16, 128>>>(input, out, 0, N);   // x -> out[:, 0:64]
    attn  <<<(N + 7) / 8, 256>>>(neigh, ee, a, out, N); // agg -> g_agg, h_edge -> out[:,128:160]
    gemm16<<<(N + 15) / 16, 128>>>(nullptr, out, 1, N); // h' -> out[:, 64:128]
}

// round 4
// speedup vs baseline: 1.6540x; 1.5480x over previous
#include <cuda_runtime.h>

#define SS   16
#define IND  128
#define OUTD 64
#define ED   32
#define OSTR 160    // output row: [x(64) | h_prime(64) | h_edge(32)]

// ---- device-global scratch (allocation-free) ----
__device__ float g_w2a[IND];                 // W2 @ a_n
__device__ float g_wax[IND];                 // W  @ a_x
__device__ float g_agg[50176 * IND];         // attention-aggregated 128-dim vectors

// ---------------------------------------------------------------------------
// Prelude: wax = W @ a_x ; w2a = W2 @ a_n
// ---------------------------------------------------------------------------
__global__ void prelude(const float* __restrict__ W, const float* __restrict__ W2,
                        const float* __restrict__ a) {
    int k = threadIdx.x;                       // 0..127
    float s1 = 0.f, s2 = 0.f;
#pragma unroll
    for (int d = 0; d < OUTD; ++d) {
        s1 = fmaf(W [k * OUTD + d], a[d],        s1);
        s2 = fmaf(W2[k * OUTD + d], a[OUTD + d], s2);
    }
    g_wax[k] = s1;
    g_w2a[k] = s2;
}

// ---------------------------------------------------------------------------
// Register-tiled GEMM: Y[m, yoff+c] = X[m,:] @ Wg[:,c]
// Mtile=64, 128 threads, 8 rows x 4 cols per thread (32 accs).
// ---------------------------------------------------------------------------
__global__ __launch_bounds__(128)
void gemm_tile(const float* __restrict__ Xp, const float* __restrict__ Wg,
               float* __restrict__ Y, int yoff, int mode, int M) {
    __shared__ float s_x[64][129];             // 33 KB

    const float* X = mode ? (const float*)g_agg : Xp;
    const int t  = threadIdx.x;
    const int m0 = blockIdx.x * 64;
    const int nv = min(64, M - m0);

    for (int i = t; i < 64 * 32; i += 128) {
        int m = i >> 5, j = i & 31;            // j = k4
        float4 v = make_float4(0.f, 0.f, 0.f, 0.f);
        if (m < nv) v = ((const float4*)X)[(size_t)(m0 + m) * 32 + j];
        s_x[m][4 * j + 0] = v.x;
        s_x[m][4 * j + 1] = v.y;
        s_x[m][4 * j + 2] = v.z;
        s_x[m][4 * j + 3] = v.w;
    }
    __syncthreads();

    const int cg = t & 15, mg = t >> 4;        // 16 col-groups x 8 row-groups
    const int c0 = cg * 4;
    const float* wp = Wg + c0;                 // row stride OUTD

    float acc[8][4];
#pragma unroll
    for (int r = 0; r < 8; ++r)
#pragma unroll
        for (int c = 0; c < 4; ++c) acc[r][c] = 0.f;

    const float* xb = &s_x[mg * 8][0];
    float4 w = *(const float4*)wp;             // k = 0 prefetch

#pragma unroll 4
    for (int k = 0; k < IND; ++k) {
        float4 wn;
        if (k + 1 < IND) wn = *(const float4*)(wp + (k + 1) * OUTD);
        float xv[8];
#pragma unroll
        for (int r = 0; r < 8; ++r) xv[r] = xb[r * 129 + k];   // bcast, conflict-free
#pragma unroll
        for (int r = 0; r < 8; ++r) {
            acc[r][0] = fmaf(xv[r], w.x, acc[r][0]);
            acc[r][1] = fmaf(xv[r], w.y, acc[r][1]);
            acc[r][2] = fmaf(xv[r], w.z, acc[r][2]);
            acc[r][3] = fmaf(xv[r], w.w, acc[r][3]);
        }
        w = wn;
    }

#pragma unroll
    for (int r = 0; r < 8; ++r) {
        int m = mg * 8 + r;
        if (m < nv)
            *(float4*)(Y + (size_t)(m0 + m) * OSTR + yoff + c0) = *(float4*)acc[r];
    }
}

// ---------------------------------------------------------------------------
// Attention: warp-per-node online softmax, single streaming pass, PF=4 ring.
// ---------------------------------------------------------------------------
#define PF 4
__global__ __launch_bounds__(256)
void attn(const float* __restrict__ input, const float* __restrict__ neigh,
          const float* __restrict__ ee, const float* __restrict__ a,
          float* __restrict__ out, int N) {
    const int w    = threadIdx.x >> 5;
    const int lane = threadIdx.x & 31;
    const int n    = blockIdx.x * 8 + w;
    if (n >= N) return;                        // whole-warp exit

    const float4* nb = (const float4*)neigh + (size_t)n * (SS * IND / 4);
    const float*  eb = ee + (size_t)n * (SS * ED);

    float4 v[PF]; float ev[PF];
#pragma unroll
    for (int i = 0; i < PF; ++i) {
        v[i]  = nb[i * (IND / 4) + lane];
        ev[i] = eb[i * ED + lane];
    }

    // sx = input_row . (W @ a_x)
    float4 xi  = ((const float4*)input)[(size_t)n * (IND / 4) + lane];
    float4 wax = ((const float4*)g_wax)[lane];
    float p = xi.x * wax.x;
    p = fmaf(xi.y, wax.y, p);
    p = fmaf(xi.z, wax.z, p);
    p = fmaf(xi.w, wax.w, p);
#pragma unroll
    for (int o = 16; o; o >>= 1) p += __shfl_xor_sync(0xffffffffu, p, o);
    const float sx = p;

    const float4 w2a4 = ((const float4*)g_w2a)[lane];
    const float  ae   = a[2 * OUTD + lane];

    float  m = -3.0e38f, den = 0.f, he = 0.f;
    float4 agg = make_float4(0.f, 0.f, 0.f, 0.f);

#pragma unroll
    for (int s = 0; s < SS; ++s) {
        const int slot = s & (PF - 1);
        float4 cv = v[slot];
        float  ce = ev[slot];
        if (s + PF < SS) {                     // refill ring slot
            v[slot]  = nb[(s + PF) * (IND / 4) + lane];
            ev[slot] = eb[(s + PF) * ED + lane];
        }

        float part = cv.x * w2a4.x;
        part = fmaf(cv.y, w2a4.y, part);
        part = fmaf(cv.z, w2a4.z, part);
        part = fmaf(cv.w, w2a4.w, part);
        part = fmaf(ce, ae, part);
#pragma unroll
        for (int o = 16; o; o >>= 1) part += __shfl_xor_sync(0xffffffffu, part, o);

        float sc = part + sx;
        sc = sc > 0.f ? sc : 0.8f * sc;        // leaky relu

        float mn   = fmaxf(m, sc);
        float corr = __expf(m - mn);
        float pe   = __expf(sc - mn);
        den   = fmaf(den,   corr, pe);
        agg.x = fmaf(agg.x, corr, pe * cv.x);
        agg.y = fmaf(agg.y, corr, pe * cv.y);
        agg.z = fmaf(agg.z, corr, pe * cv.z);
        agg.w = fmaf(agg.w, corr, pe * cv.w);
        he    = fmaf(he,    corr, pe * ce);
        m = mn;
    }

    const float inv = 1.f / den;
    float4 o4 = make_float4(agg.x * inv, agg.y * inv, agg.z * inv, agg.w * inv);
    ((float4*)g_agg)[(size_t)n * (IND / 4) + lane] = o4;
    out[(size_t)n * OSTR + 2 * OUTD + lane] = he * inv;
}

// ---------------------------------------------------------------------------
extern "C" void kernel_launch(void* const* d_in, const int* in_sizes, int n_in,
                              void* d_out, int out_size) {
    const float* input = (const float*)d_in[0];
    const float* neigh = (const float*)d_in[1];
    const float* ee    = (const float*)d_in[2];
    const float* W     = (const float*)d_in[3];
    const float* W2    = (const float*)d_in[4];
    const float* a     = (const float*)d_in[5];
    float* out = (float*)d_out;

    const int N = in_sizes[0] / IND;           // 50000

    prelude<<<1, 128>>>(W, W2, a);
    gemm_tile<<<(N + 63) / 64, 128>>>(input, W, out, 0, 0, N);       // x -> out[:,0:64]
    attn<<<(N + 7) / 8, 256>>>(input, neigh, ee, a, out, N);         // agg, h_edge
    gemm_tile<<<(N + 63) / 64, 128>>>(nullptr, W2, out, OUTD, 1, N); // h' -> out[:,64:128]
}